// round 8
// baseline (speedup 1.0000x reference)
#include <cuda_runtime.h>

#define BB 16
#define NTOK 2049
#define NK 2048
#define CC 1024
#define WS 3072
#define NTILES 2048            // 16 b x 128 tiles of 16 rows

__device__ float g_qp[32 * BB * CC];   // q_cls partials: [dslice][b][c]
__device__ float g_qcls[BB * CC];
__device__ float g_v[BB * CC];
__device__ float g_psum[BB * 1024];    // exp partials: [b][tile*8+warp]
__device__ int   g_ticket = 0;

// ---------------------------------------------------------------------------
// K1: q_cls partials. grid (8 c-tiles, 32 d-slices), 256 thr.
// W_q read exactly once chip-wide.
// ---------------------------------------------------------------------------
__global__ __launch_bounds__(256) void k_qcls(const float* __restrict__ x,
                                              const float* __restrict__ w) {
    __shared__ float xs[16 * 32];        // [b][dd]
    __shared__ float red[4 * 16 * 128];  // [dg][b][c] 32KB
    const int t  = threadIdx.x;
    const int d0 = blockIdx.y * 32;
    const int c0 = blockIdx.x * 128;

    if (t < 128) {   // stage x token-0 slices: 512 floats = 128 float4
        const int b = t >> 3, dd = (t & 7) * 4;
        *(float4*)&xs[b * 32 + dd] =
            *(const float4*)&x[(size_t)b * NTOK * CC + d0 + dd];
    }
    __syncthreads();

    const int wid = t >> 5, lane = t & 31;
    const int dg = wid & 3, bg = wid >> 2;
    const int c = c0 + lane * 4;

    float4 a[8];
    #pragma unroll
    for (int j = 0; j < 8; j++) a[j] = make_float4(0.f, 0.f, 0.f, 0.f);

    const float* xb = &xs[bg * 8 * 32];
    #pragma unroll
    for (int i = 0; i < 8; i++) {
        const int dd = dg * 8 + i;
        const float4 w4 = *(const float4*)&w[(size_t)(d0 + dd) * WS + c];
        #pragma unroll
        for (int j = 0; j < 8; j++) {
            const float xv = xb[j * 32 + dd];
            a[j].x = fmaf(w4.x, xv, a[j].x);
            a[j].y = fmaf(w4.y, xv, a[j].y);
            a[j].z = fmaf(w4.z, xv, a[j].z);
            a[j].w = fmaf(w4.w, xv, a[j].w);
        }
    }
    #pragma unroll
    for (int j = 0; j < 8; j++)
        *(float4*)&red[dg * 2048 + (bg * 8 + j) * 128 + lane * 4] = a[j];
    __syncthreads();

    #pragma unroll
    for (int k = 0; k < 8; k++) {
        const int idx = t + 256 * k;
        const float s = (red[idx] + red[idx + 2048])
                      + (red[idx + 4096] + red[idx + 6144]);
        g_qp[(blockIdx.y * 16 + (idx >> 7)) * CC + c0 + (idx & 127)] = s;
    }
}

// ---------------------------------------------------------------------------
// K1b: collapse 32 d-slice partials. grid (8,16), 128 thr.
// ---------------------------------------------------------------------------
__global__ __launch_bounds__(128) void k_qred() {
    const int b = blockIdx.y;
    const int c = blockIdx.x * 128 + threadIdx.x;
    float s = 0.f;
    #pragma unroll
    for (int ds = 0; ds < 32; ds++) s += g_qp[(ds * 16 + b) * CC + c];
    g_qcls[b * CC + c] = s;
}

// ---------------------------------------------------------------------------
// K2: v[b,d] = W_k[d,:] . q_cls[b,:]
// grid (64, 2), 512 thr = 16 warps, warp per d, 8 batches/warp.
// Also resets the K3 work-stealing ticket (stream-ordered before K3).
// ---------------------------------------------------------------------------
__global__ __launch_bounds__(512) void k_v(const float* __restrict__ w) {
    __shared__ float qs[8 * CC];
    if (blockIdx.x == 0 && blockIdx.y == 0 && threadIdx.x == 0) g_ticket = 0;
    const int bg   = blockIdx.y;
    const int d    = blockIdx.x * 16 + (threadIdx.x >> 5);
    const int lane = threadIdx.x & 31;

    #pragma unroll
    for (int i = 0; i < 4; i++)
        ((float4*)qs)[threadIdx.x + 512 * i] =
            ((const float4*)(g_qcls + bg * 8 * CC))[threadIdx.x + 512 * i];
    __syncthreads();

    const float* wr = w + (size_t)d * WS + CC;
    float acc[8];
    #pragma unroll
    for (int b = 0; b < 8; b++) acc[b] = 0.f;

    #pragma unroll
    for (int i = 0; i < 8; i++) {
        const int cc = i * 128 + lane * 4;
        const float4 w4 = *(const float4*)&wr[cc];
        #pragma unroll
        for (int b = 0; b < 8; b++) {
            const float4 q4 = *(const float4*)&qs[b * CC + cc];
            acc[b] = fmaf(w4.x, q4.x, acc[b]);
            acc[b] = fmaf(w4.y, q4.y, acc[b]);
            acc[b] = fmaf(w4.z, q4.z, acc[b]);
            acc[b] = fmaf(w4.w, q4.w, acc[b]);
        }
    }
    #pragma unroll
    for (int b = 0; b < 8; b++) {
        float a = acc[b];
        #pragma unroll
        for (int o = 16; o; o >>= 1) a += __shfl_xor_sync(0xffffffffu, a, o);
        if (lane == 0) g_v[(bg * 8 + b) * CC + d] = a;
    }
}

// ---------------------------------------------------------------------------
// K3 (dominant, HBM-bound): persistent blocks + work stealing.
// grid 592 (=148x4), 256 thr. Ticket = (b, 16-row tile); 8 warps x 2 rows.
// Ticket->output and ticket->psum-slot maps fixed => bitwise deterministic.
// ---------------------------------------------------------------------------
__global__ __launch_bounds__(256) void k_logits(const float* __restrict__ x,
                                                float* __restrict__ out) {
    __shared__ float vs[CC];
    __shared__ int tk;
    const int warp = threadIdx.x >> 5;
    const int lane = threadIdx.x & 31;

    for (;;) {
        if (threadIdx.x == 0) tk = atomicAdd(&g_ticket, 1);
        __syncthreads();
        const int ticket = tk;
        if (ticket >= NTILES) break;

        const int b  = ticket >> 7;          // 128 tiles per batch
        const int n0 = (ticket & 127) * 16 + warp * 2;

        ((float4*)vs)[threadIdx.x] = ((const float4*)(g_v + b * CC))[threadIdx.x];
        __syncthreads();

        const float4* x0 = (const float4*)(x + ((size_t)b * NTOK + n0 + 1) * CC) + lane;
        float4 a0 = make_float4(0.f, 0.f, 0.f, 0.f);
        float4 a1 = a0;
        #pragma unroll
        for (int i = 0; i < 8; i++) {
            const int off = i * 32;
            const float4 xv0 = __ldcs(x0 + off);
            const float4 xv1 = __ldcs(x0 + 256 + off);
            const float4 vv  = ((const float4*)vs)[off + lane];
            a0.x = fmaf(xv0.x, vv.x, a0.x); a0.y = fmaf(xv0.y, vv.y, a0.y);
            a0.z = fmaf(xv0.z, vv.z, a0.z); a0.w = fmaf(xv0.w, vv.w, a0.w);
            a1.x = fmaf(xv1.x, vv.x, a1.x); a1.y = fmaf(xv1.y, vv.y, a1.y);
            a1.z = fmaf(xv1.z, vv.z, a1.z); a1.w = fmaf(xv1.w, vv.w, a1.w);
        }
        float s0 = (a0.x + a0.y) + (a0.z + a0.w);
        float s1 = (a1.x + a1.y) + (a1.z + a1.w);
        #pragma unroll
        for (int o = 16; o; o >>= 1) {
            s0 += __shfl_xor_sync(0xffffffffu, s0, o);
            s1 += __shfl_xor_sync(0xffffffffu, s1, o);
        }
        if (lane == 0) {
            float2 e;
            e.x = __expf(s0 * 0.03125f);
            e.y = __expf(s1 * 0.03125f);
            *(float2*)&out[(b << 11) + n0] = e;
            g_psum[b * 1024 + (ticket & 127) * 8 + warp] = e.x + e.y;
        }
        __syncthreads();   // protect vs and tk before next iteration
    }
}

// ---------------------------------------------------------------------------
// K4: normalize. grid (4, 16), 512 thr. Reduce 1024 fixed-order partials.
// ---------------------------------------------------------------------------
__global__ __launch_bounds__(512) void k_norm(float* __restrict__ out) {
    __shared__ float sp[512];
    const int b = blockIdx.y, t = threadIdx.x;
    sp[t] = g_psum[b * 1024 + t] + g_psum[b * 1024 + 512 + t];
    __syncthreads();
    #pragma unroll
    for (int o = 256; o; o >>= 1) {
        if (t < o) sp[t] += sp[t + o];
        __syncthreads();
    }
    const float inv = 1.0f / sp[0];
    const int idx = blockIdx.x * 512 + t;
    out[(b << 11) + idx] *= inv;
}

// ---------------------------------------------------------------------------
extern "C" void kernel_launch(void* const* d_in, const int* in_sizes, int n_in,
                              void* d_out, int out_size) {
    const float* x = (const float*)d_in[0];
    const float* w = (const float*)d_in[1];
    if (n_in >= 2 && in_sizes[0] == CC * WS && in_sizes[1] == BB * NTOK * CC) {
        x = (const float*)d_in[1];
        w = (const float*)d_in[0];
    }
    float* out = (float*)d_out;

    k_qcls  <<<dim3(8, 32),  256>>>(x, w);
    k_qred  <<<dim3(8, 16),  128>>>();
    k_v     <<<dim3(64, 2),  512>>>(w);
    k_logits<<<592,          256>>>(x, out);
    k_norm  <<<dim3(4, 16),  512>>>(out);
}

// round 11
// speedup vs baseline: 1.0322x; 1.0322x over previous
#include <cuda_runtime.h>
#include <cstdint>

#define BB 16
#define NTOK 2049
#define NK 2048
#define CC 1024
#define WS 3072

__device__ float g_qp[32 * BB * CC];   // q_cls partials: [dslice][b][c]
__device__ float g_qcls[BB * CC];
__device__ float g_v[BB * CC];
__device__ float g_psum[BB * 512];     // exp partials: [b][block*4+warp]

// ---------------------------------------------------------------------------
// cp.async helpers
// ---------------------------------------------------------------------------
__device__ __forceinline__ void cpa16(unsigned int smem_addr, const void* gptr) {
    asm volatile("cp.async.cg.shared.global [%0], [%1], 16;"
                 :: "r"(smem_addr), "l"(gptr));
}
#define CPA_COMMIT()  asm volatile("cp.async.commit_group;")
#define CPA_WAIT(N)   asm volatile("cp.async.wait_group %0;" :: "n"(N))

// ---------------------------------------------------------------------------
// K1: q_cls partials. grid (8 c-tiles, 32 d-slices), 256 thr.
// W_q read exactly once chip-wide.
// ---------------------------------------------------------------------------
__global__ __launch_bounds__(256) void k_qcls(const float* __restrict__ x,
                                              const float* __restrict__ w) {
    __shared__ float xs[16 * 32];
    __shared__ float red[4 * 16 * 128];
    const int t  = threadIdx.x;
    const int d0 = blockIdx.y * 32;
    const int c0 = blockIdx.x * 128;

    if (t < 128) {
        const int b = t >> 3, dd = (t & 7) * 4;
        *(float4*)&xs[b * 32 + dd] =
            *(const float4*)&x[(size_t)b * NTOK * CC + d0 + dd];
    }
    __syncthreads();

    const int wid = t >> 5, lane = t & 31;
    const int dg = wid & 3, bg = wid >> 2;
    const int c = c0 + lane * 4;

    float4 a[8];
    #pragma unroll
    for (int j = 0; j < 8; j++) a[j] = make_float4(0.f, 0.f, 0.f, 0.f);

    const float* xb = &xs[bg * 8 * 32];
    #pragma unroll
    for (int i = 0; i < 8; i++) {
        const int dd = dg * 8 + i;
        const float4 w4 = *(const float4*)&w[(size_t)(d0 + dd) * WS + c];
        #pragma unroll
        for (int j = 0; j < 8; j++) {
            const float xv = xb[j * 32 + dd];
            a[j].x = fmaf(w4.x, xv, a[j].x);
            a[j].y = fmaf(w4.y, xv, a[j].y);
            a[j].z = fmaf(w4.z, xv, a[j].z);
            a[j].w = fmaf(w4.w, xv, a[j].w);
        }
    }
    #pragma unroll
    for (int j = 0; j < 8; j++)
        *(float4*)&red[dg * 2048 + (bg * 8 + j) * 128 + lane * 4] = a[j];
    __syncthreads();

    #pragma unroll
    for (int k = 0; k < 8; k++) {
        const int idx = t + 256 * k;
        const float s = (red[idx] + red[idx + 2048])
                      + (red[idx + 4096] + red[idx + 6144]);
        g_qp[(blockIdx.y * 16 + (idx >> 7)) * CC + c0 + (idx & 127)] = s;
    }
}

// ---------------------------------------------------------------------------
// K1b: collapse 32 d-slice partials. grid (8,16), 128 thr.
// ---------------------------------------------------------------------------
__global__ __launch_bounds__(128) void k_qred() {
    const int b = blockIdx.y;
    const int c = blockIdx.x * 128 + threadIdx.x;
    float s = 0.f;
    #pragma unroll
    for (int ds = 0; ds < 32; ds++) s += g_qp[(ds * 16 + b) * CC + c];
    g_qcls[b * CC + c] = s;
}

// ---------------------------------------------------------------------------
// K2: v[b,d] = W_k[d,:] . q_cls[b,:]
// grid (64, 2), 512 thr = 16 warps, warp per d, 8 batches/warp.
// ---------------------------------------------------------------------------
__global__ __launch_bounds__(512) void k_v(const float* __restrict__ w) {
    __shared__ float qs[8 * CC];
    const int bg   = blockIdx.y;
    const int d    = blockIdx.x * 16 + (threadIdx.x >> 5);
    const int lane = threadIdx.x & 31;

    #pragma unroll
    for (int i = 0; i < 4; i++)
        ((float4*)qs)[threadIdx.x + 512 * i] =
            ((const float4*)(g_qcls + bg * 8 * CC))[threadIdx.x + 512 * i];
    __syncthreads();

    const float* wr = w + (size_t)d * WS + CC;
    float acc[8];
    #pragma unroll
    for (int b = 0; b < 8; b++) acc[b] = 0.f;

    #pragma unroll
    for (int i = 0; i < 8; i++) {
        const int cc = i * 128 + lane * 4;
        const float4 w4 = *(const float4*)&wr[cc];
        #pragma unroll
        for (int b = 0; b < 8; b++) {
            const float4 q4 = *(const float4*)&qs[b * CC + cc];
            acc[b] = fmaf(w4.x, q4.x, acc[b]);
            acc[b] = fmaf(w4.y, q4.y, acc[b]);
            acc[b] = fmaf(w4.z, q4.z, acc[b]);
            acc[b] = fmaf(w4.w, q4.w, acc[b]);
        }
    }
    #pragma unroll
    for (int b = 0; b < 8; b++) {
        float a = acc[b];
        #pragma unroll
        for (int o = 16; o; o >>= 1) a += __shfl_xor_sync(0xffffffffu, a, o);
        if (lane == 0) g_v[(bg * 8 + b) * CC + d] = a;
    }
}

// ---------------------------------------------------------------------------
// K3 (dominant, HBM-bound): cp.async pipelined GEMV.
// grid (128, 16), 128 thr (4 warps). Block = 16 rows = 4 tiles x 4 rows.
// 2-stage smem ring (2 x 16KB) + v staged to smem then held in registers.
// Warp w computes row (tile*4 + w); exp + psum epilogue per row.
// ---------------------------------------------------------------------------
__global__ __launch_bounds__(128) void k_logits(const float* __restrict__ x,
                                                float* __restrict__ out) {
    __shared__ float tiles[2 * 4096];
    __shared__ float vsm[CC];
    const int b    = blockIdx.y;
    const int bx   = blockIdx.x;
    const int tid  = threadIdx.x;
    const int warp = tid >> 5;
    const int lane = tid & 31;

    // stage v -> smem -> registers (row-invariant across all tiles)
    #pragma unroll
    for (int i = 0; i < 2; i++)
        ((float4*)vsm)[tid + 128 * i] = ((const float4*)(g_v + b * CC))[tid + 128 * i];

    const float* xbase = x + ((size_t)b * NTOK + bx * 16 + 1) * CC;
    const unsigned int sb = (unsigned int)__cvta_generic_to_shared(tiles);

    // prologue: issue tiles 0 and 1
    #pragma unroll
    for (int k = 0; k < 8; k++)
        cpa16(sb + (k * 512 + tid * 4) * 4, xbase + k * 512 + tid * 4);
    CPA_COMMIT();
    #pragma unroll
    for (int k = 0; k < 8; k++)
        cpa16(sb + (4096 + k * 512 + tid * 4) * 4, xbase + 4096 + k * 512 + tid * 4);
    CPA_COMMIT();

    __syncthreads();          // vsm ready
    float4 vr[8];
    #pragma unroll
    for (int i = 0; i < 8; i++) vr[i] = ((const float4*)vsm)[i * 32 + lane];

    float psum = 0.f;

    #pragma unroll
    for (int t = 0; t < 4; t++) {
        if (t == 3) { CPA_WAIT(0); } else { CPA_WAIT(1); }
        __syncthreads();      // tile t visible to all threads

        const float* buf = tiles + (t & 1) * 4096 + warp * CC;
        float4 a = make_float4(0.f, 0.f, 0.f, 0.f);
        #pragma unroll
        for (int i = 0; i < 8; i++) {
            const float4 xv = ((const float4*)buf)[i * 32 + lane];
            a.x = fmaf(xv.x, vr[i].x, a.x);
            a.y = fmaf(xv.y, vr[i].y, a.y);
            a.z = fmaf(xv.z, vr[i].z, a.z);
            a.w = fmaf(xv.w, vr[i].w, a.w);
        }
        float s = (a.x + a.y) + (a.z + a.w);
        #pragma unroll
        for (int o = 16; o; o >>= 1) s += __shfl_xor_sync(0xffffffffu, s, o);

        if (lane == 0) {
            const float e = __expf(s * 0.03125f);
            out[(b << 11) + bx * 16 + t * 4 + warp] = e;
            psum += e;
        }

        if (t < 2) {
            __syncthreads();  // all readers done with buf (t&1) before overwrite
            const int nt = t + 2;
            #pragma unroll
            for (int k = 0; k < 8; k++)
                cpa16(sb + ((nt & 1) * 4096 + k * 512 + tid * 4) * 4,
                      xbase + nt * 4096 + k * 512 + tid * 4);
            CPA_COMMIT();
        }
    }

    if (lane == 0)
        g_psum[b * 512 + bx * 4 + warp] = psum;
}

// ---------------------------------------------------------------------------
// K4: normalize. grid (4, 16), 512 thr. Reduce 512 fixed-order partials.
// ---------------------------------------------------------------------------
__global__ __launch_bounds__(512) void k_norm(float* __restrict__ out) {
    __shared__ float sp[512];
    const int b = blockIdx.y, t = threadIdx.x;
    sp[t] = g_psum[b * 512 + t];
    __syncthreads();
    #pragma unroll
    for (int o = 256; o; o >>= 1) {
        if (t < o) sp[t] += sp[t + o];
        __syncthreads();
    }
    const float inv = 1.0f / sp[0];
    const int idx = blockIdx.x * 512 + t;
    out[(b << 11) + idx] *= inv;
}

// ---------------------------------------------------------------------------
extern "C" void kernel_launch(void* const* d_in, const int* in_sizes, int n_in,
                              void* d_out, int out_size) {
    const float* x = (const float*)d_in[0];
    const float* w = (const float*)d_in[1];
    if (n_in >= 2 && in_sizes[0] == CC * WS && in_sizes[1] == BB * NTOK * CC) {
        x = (const float*)d_in[1];
        w = (const float*)d_in[0];
    }
    float* out = (float*)d_out;

    k_qcls  <<<dim3(8, 32),   256>>>(x, w);
    k_qred  <<<dim3(8, 16),   128>>>();
    k_v     <<<dim3(64, 2),   512>>>(w);
    k_logits<<<dim3(128, 16), 128>>>(x, out);
    k_norm  <<<dim3(4, 16),   512>>>(out);
}

// round 12
// speedup vs baseline: 1.0507x; 1.0180x over previous
#include <cuda_runtime.h>
#include <cstdint>

#define BB 16
#define NTOK 2049
#define NK 2048
#define CC 1024
#define WS 3072

__device__ float g_qcls[BB * CC];      // zero-init; atomically accumulated; re-zeroed by k_norm
__device__ float g_v[BB * CC];
__device__ float g_psum[BB * 256];     // exp partials: [b][block*4+warp]

// ---------------------------------------------------------------------------
// cp.async helpers
// ---------------------------------------------------------------------------
__device__ __forceinline__ void cpa16(unsigned int smem_addr, const void* gptr) {
    asm volatile("cp.async.cg.shared.global [%0], [%1], 16;"
                 :: "r"(smem_addr), "l"(gptr));
}
#define CPA_COMMIT()  asm volatile("cp.async.commit_group;")
#define CPA_WAIT(N)   asm volatile("cp.async.wait_group %0;" :: "n"(N))

// ---------------------------------------------------------------------------
// K1: q_cls accumulation. grid (8 c-tiles, 16 d-slices), 256 thr.
// W_q read exactly once chip-wide; block-reduced partials atomicAdd'ed
// into g_qcls (pre-zeroed).
// ---------------------------------------------------------------------------
__global__ __launch_bounds__(256) void k_qcls(const float* __restrict__ x,
                                              const float* __restrict__ w) {
    __shared__ float xs[16 * 64];        // [b][dd]
    __shared__ float red[4 * 16 * 128];  // [dg][b][c]
    const int t  = threadIdx.x;
    const int d0 = blockIdx.y * 64;
    const int c0 = blockIdx.x * 128;

    {
        const int b = t >> 4, dd = (t & 15) * 4;
        *(float4*)&xs[b * 64 + dd] =
            *(const float4*)&x[(size_t)b * NTOK * CC + d0 + dd];
    }
    __syncthreads();

    const int wid = t >> 5, lane = t & 31;
    const int dg = wid & 3, bg = wid >> 2;
    const int c = c0 + lane * 4;

    float4 a[8];
    #pragma unroll
    for (int j = 0; j < 8; j++) a[j] = make_float4(0.f, 0.f, 0.f, 0.f);

    const float* xb = &xs[bg * 8 * 64];
    #pragma unroll
    for (int i = 0; i < 16; i++) {
        const int dd = dg * 16 + i;
        const float4 w4 = *(const float4*)&w[(size_t)(d0 + dd) * WS + c];
        #pragma unroll
        for (int j = 0; j < 8; j++) {
            const float xv = xb[j * 64 + dd];
            a[j].x = fmaf(w4.x, xv, a[j].x);
            a[j].y = fmaf(w4.y, xv, a[j].y);
            a[j].z = fmaf(w4.z, xv, a[j].z);
            a[j].w = fmaf(w4.w, xv, a[j].w);
        }
    }
    #pragma unroll
    for (int j = 0; j < 8; j++)
        *(float4*)&red[dg * 2048 + (bg * 8 + j) * 128 + lane * 4] = a[j];
    __syncthreads();

    #pragma unroll
    for (int k = 0; k < 8; k++) {
        const int idx = t + 256 * k;                 // b = idx>>7, c = idx&127
        const float s = (red[idx] + red[idx + 2048])
                      + (red[idx + 4096] + red[idx + 6144]);
        atomicAdd(&g_qcls[(idx >> 7) * CC + c0 + (idx & 127)], s);
    }
}

// ---------------------------------------------------------------------------
// K2: v[b,d] = W_k[d,:] . q_cls[b,:]
// grid (64, 2), 512 thr = 16 warps, warp per d, 8 batches/warp.
// ---------------------------------------------------------------------------
__global__ __launch_bounds__(512) void k_v(const float* __restrict__ w) {
    __shared__ float qs[8 * CC];
    const int bg   = blockIdx.y;
    const int d    = blockIdx.x * 16 + (threadIdx.x >> 5);
    const int lane = threadIdx.x & 31;

    #pragma unroll
    for (int i = 0; i < 4; i++)
        ((float4*)qs)[threadIdx.x + 512 * i] =
            ((const float4*)(g_qcls + bg * 8 * CC))[threadIdx.x + 512 * i];
    __syncthreads();

    const float* wr = w + (size_t)d * WS + CC;
    float acc[8];
    #pragma unroll
    for (int b = 0; b < 8; b++) acc[b] = 0.f;

    #pragma unroll
    for (int i = 0; i < 8; i++) {
        const int cc = i * 128 + lane * 4;
        const float4 w4 = *(const float4*)&wr[cc];
        #pragma unroll
        for (int b = 0; b < 8; b++) {
            const float4 q4 = *(const float4*)&qs[b * CC + cc];
            acc[b] = fmaf(w4.x, q4.x, acc[b]);
            acc[b] = fmaf(w4.y, q4.y, acc[b]);
            acc[b] = fmaf(w4.z, q4.z, acc[b]);
            acc[b] = fmaf(w4.w, q4.w, acc[b]);
        }
    }
    #pragma unroll
    for (int b = 0; b < 8; b++) {
        float a = acc[b];
        #pragma unroll
        for (int o = 16; o; o >>= 1) a += __shfl_xor_sync(0xffffffffu, a, o);
        if (lane == 0) g_v[(bg * 8 + b) * CC + d] = a;
    }
}

// ---------------------------------------------------------------------------
// K3 (dominant, HBM-bound): warp-independent cp.async pipelines.
// grid (64, 16), 128 thr (4 warps). Each warp: 8 rows, private 2x4KB
// double buffer, no block barriers in steady state.
// ---------------------------------------------------------------------------
__global__ __launch_bounds__(128) void k_logits(const float* __restrict__ x,
                                                float* __restrict__ out) {
    __shared__ float buf[4][2][CC];
    __shared__ float vsm[CC];
    const int b    = blockIdx.y;
    const int bx   = blockIdx.x;
    const int tid  = threadIdx.x;
    const int warp = tid >> 5;
    const int lane = tid & 31;

    // stage v -> smem
    ((float4*)vsm)[tid]       = ((const float4*)(g_v + b * CC))[tid];
    ((float4*)vsm)[tid + 128] = ((const float4*)(g_v + b * CC))[tid + 128];

    const int row0 = bx * 32 + warp * 8;                   // this warp's rows
    const char* xw = (const char*)(x + ((size_t)b * NTOK + row0 + 1) * CC);
    const unsigned int sb =
        (unsigned int)__cvta_generic_to_shared(&buf[warp][0][0]);

    // prologue: rows 0 and 1 of this warp
    #pragma unroll
    for (int k = 0; k < 8; k++)
        cpa16(sb + k * 512 + lane * 16, xw + k * 512 + lane * 16);
    CPA_COMMIT();
    #pragma unroll
    for (int k = 0; k < 8; k++)
        cpa16(sb + 4096 + k * 512 + lane * 16, xw + 4096 + k * 512 + lane * 16);
    CPA_COMMIT();

    __syncthreads();          // vsm ready (single block barrier)
    float4 vr[8];
    #pragma unroll
    for (int i = 0; i < 8; i++) vr[i] = ((const float4*)vsm)[i * 32 + lane];

    float psum = 0.f;

    #pragma unroll
    for (int r = 0; r < 8; r++) {
        if (r == 7) { CPA_WAIT(0); } else { CPA_WAIT(1); }
        __syncwarp();

        const float4* bp = (const float4*)&buf[warp][r & 1][0];
        float4 a = make_float4(0.f, 0.f, 0.f, 0.f);
        #pragma unroll
        for (int i = 0; i < 8; i++) {
            const float4 xv = bp[i * 32 + lane];
            a.x = fmaf(xv.x, vr[i].x, a.x);
            a.y = fmaf(xv.y, vr[i].y, a.y);
            a.z = fmaf(xv.z, vr[i].z, a.z);
            a.w = fmaf(xv.w, vr[i].w, a.w);
        }
        float s = (a.x + a.y) + (a.z + a.w);
        #pragma unroll
        for (int o = 16; o; o >>= 1) s += __shfl_xor_sync(0xffffffffu, s, o);

        if (lane == 0) {
            const float e = __expf(s * 0.03125f);
            out[(b << 11) + row0 + r] = e;
            psum += e;
        }
        __syncwarp();         // all lanes done reading buf before overwrite

        if (r < 6) {
            const unsigned int dst = sb + (r & 1) * 4096;
            const char* src = xw + (size_t)(r + 2) * 4096;
            #pragma unroll
            for (int k = 0; k < 8; k++)
                cpa16(dst + k * 512 + lane * 16, src + k * 512 + lane * 16);
            CPA_COMMIT();
        }
    }

    if (lane == 0)
        g_psum[b * 256 + bx * 4 + warp] = psum;
}

// ---------------------------------------------------------------------------
// K4: normalize + re-zero g_qcls for the next call.
// grid (8, 16), 256 thr. Reduce 256 fixed-order partials.
// ---------------------------------------------------------------------------
__global__ __launch_bounds__(256) void k_norm(float* __restrict__ out) {
    __shared__ float sp[256];
    const int b = blockIdx.y, t = threadIdx.x;
    sp[t] = g_psum[b * 256 + t];
    __syncthreads();
    #pragma unroll
    for (int o = 128; o; o >>= 1) {
        if (t < o) sp[t] += sp[t + o];
        __syncthreads();
    }
    const float inv = 1.0f / sp[0];
    const int idx = blockIdx.x * 256 + t;
    out[(b << 11) + idx] *= inv;

    // re-zero g_qcls (16384 floats) for the next launch
    const int flat = (b * 8 + blockIdx.x) * 256 + t;
    if (flat < BB * CC) g_qcls[flat] = 0.f;
}

// ---------------------------------------------------------------------------
extern "C" void kernel_launch(void* const* d_in, const int* in_sizes, int n_in,
                              void* d_out, int out_size) {
    const float* x = (const float*)d_in[0];
    const float* w = (const float*)d_in[1];
    if (n_in >= 2 && in_sizes[0] == CC * WS && in_sizes[1] == BB * NTOK * CC) {
        x = (const float*)d_in[1];
        w = (const float*)d_in[0];
    }
    float* out = (float*)d_out;

    k_qcls  <<<dim3(8, 16),  256>>>(x, w);
    k_v     <<<dim3(64, 2),  512>>>(w);
    k_logits<<<dim3(64, 16), 128>>>(x, out);
    k_norm  <<<dim3(8, 16),  256>>>(out);
}

// round 13
// speedup vs baseline: 1.0549x; 1.0039x over previous
#include <cuda_runtime.h>
#include <cstdint>

#define BB 16
#define NTOK 2049
#define NK 2048
#define CC 1024
#define WS 3072

__device__ float g_qcls[BB * CC];      // zero-init; atomically accumulated; re-zeroed in k_prep
__device__ float g_v[BB * CC];
__device__ float g_psum[BB * 128];     // exp partials: [b][blk*4+warp]
__device__ unsigned g_barP = 0;        // prep barrier counter (monotonic)
__device__ unsigned g_barL = 0;        // logits barrier counter (monotonic)

// ---------------------------------------------------------------------------
// helpers
// ---------------------------------------------------------------------------
__device__ __forceinline__ void cpa16(unsigned int smem_addr, const void* gptr) {
    asm volatile("cp.async.cg.shared.global [%0], [%1], 16;"
                 :: "r"(smem_addr), "l"(gptr));
}
#define CPA_COMMIT()  asm volatile("cp.async.commit_group;")
#define CPA_WAIT(N)   asm volatile("cp.async.wait_group %0;" :: "n"(N))

// Grid barrier via monotonic counter: each launch adds exactly G arrivals,
// so target = ceil(my/G)*G. Works across CUDA-graph replays with no reset.
__device__ __forceinline__ void gridbar(unsigned* ctr, unsigned G) {
    __shared__ unsigned tgt_s;
    __syncthreads();
    __threadfence();
    if (threadIdx.x == 0) {
        const unsigned my = atomicAdd(ctr, 1u) + 1u;
        const unsigned tgt = ((my - 1u) / G + 1u) * G;
        while (atomicAdd(ctr, 0u) < tgt) __nanosleep(64);
        tgt_s = tgt;   // dummy use to keep it live
    }
    __syncthreads();
    __threadfence();
    (void)tgt_s;
}

// ---------------------------------------------------------------------------
// k_prep: fused q_cls + v. grid 128, 256 thr (all resident => barrier safe).
// Phase A: q_cls partials, W_q read exactly once chip-wide, atomicAdd.
// Phase B: v[b,d] = W_k[d,:].q_cls[b,:], warp per d, two 8-batch passes.
// Phase C: re-zero g_qcls for next replay.
// ---------------------------------------------------------------------------
__global__ __launch_bounds__(256) void k_prep(const float* __restrict__ x,
                                              const float* __restrict__ w) {
    __shared__ float pool[9216];          // A: xs[1024]+red[8192]; B: qs[8192]
    const int t   = threadIdx.x;
    const int bid = blockIdx.x;
    const int wid = t >> 5, lane = t & 31;

    // ---------------- Phase A: q_cls partials ----------------
    {
        float* xs  = pool;                // [b][dd] 16x64
        float* red = pool + 1024;         // [dg][b][c] 4x16x128
        const int d0 = (bid >> 3) * 64;
        const int c0 = (bid & 7) * 128;

        {
            const int b = t >> 4, dd = (t & 15) * 4;
            *(float4*)&xs[b * 64 + dd] =
                *(const float4*)&x[(size_t)b * NTOK * CC + d0 + dd];
        }
        __syncthreads();

        const int dg = wid & 3, bg = wid >> 2;
        const int c = c0 + lane * 4;

        float4 a[8];
        #pragma unroll
        for (int j = 0; j < 8; j++) a[j] = make_float4(0.f, 0.f, 0.f, 0.f);

        const float* xb = &xs[bg * 8 * 64];
        #pragma unroll
        for (int i = 0; i < 16; i++) {
            const int dd = dg * 16 + i;
            const float4 w4 = *(const float4*)&w[(size_t)(d0 + dd) * WS + c];
            #pragma unroll
            for (int j = 0; j < 8; j++) {
                const float xv = xb[j * 64 + dd];
                a[j].x = fmaf(w4.x, xv, a[j].x);
                a[j].y = fmaf(w4.y, xv, a[j].y);
                a[j].z = fmaf(w4.z, xv, a[j].z);
                a[j].w = fmaf(w4.w, xv, a[j].w);
            }
        }
        #pragma unroll
        for (int j = 0; j < 8; j++)
            *(float4*)&red[dg * 2048 + (bg * 8 + j) * 128 + lane * 4] = a[j];
        __syncthreads();

        #pragma unroll
        for (int k = 0; k < 8; k++) {
            const int idx = t + 256 * k;             // b = idx>>7, c = idx&127
            const float s = (red[idx] + red[idx + 2048])
                          + (red[idx + 4096] + red[idx + 6144]);
            atomicAdd(&g_qcls[(idx >> 7) * CC + c0 + (idx & 127)], s);
        }
    }

    gridbar(&g_barP, 128);

    // ---------------- Phase B: v ----------------
    {
        float* qs = pool;                 // 8 batches x 1024
        const int d = bid * 8 + wid;      // one warp per d (1024 total)
        const float* wr = w + (size_t)d * WS + CC;

        #pragma unroll
        for (int bg = 0; bg < 2; bg++) {
            __syncthreads();
            #pragma unroll
            for (int i = 0; i < 8; i++)
                ((float4*)qs)[t + 256 * i] =
                    ((const float4*)(g_qcls + bg * 8 * CC))[t + 256 * i];
            __syncthreads();

            float acc[8];
            #pragma unroll
            for (int b = 0; b < 8; b++) acc[b] = 0.f;

            #pragma unroll
            for (int i = 0; i < 8; i++) {
                const int cc = i * 128 + lane * 4;
                const float4 w4 = *(const float4*)&wr[cc];
                #pragma unroll
                for (int b = 0; b < 8; b++) {
                    const float4 q4 = *(const float4*)&qs[b * CC + cc];
                    acc[b] = fmaf(w4.x, q4.x, acc[b]);
                    acc[b] = fmaf(w4.y, q4.y, acc[b]);
                    acc[b] = fmaf(w4.z, q4.z, acc[b]);
                    acc[b] = fmaf(w4.w, q4.w, acc[b]);
                }
            }
            #pragma unroll
            for (int b = 0; b < 8; b++) {
                float a = acc[b];
                #pragma unroll
                for (int o = 16; o; o >>= 1) a += __shfl_xor_sync(0xffffffffu, a, o);
                if (lane == 0) g_v[(bg * 8 + b) * CC + d] = a;
            }
        }
    }

    gridbar(&g_barP, 128);

    // ---------------- Phase C: re-zero g_qcls ----------------
    {
        const int flat = bid * 256 + t;   // 32768 threads, first 16384 zero
        if (flat < BB * CC) g_qcls[flat] = 0.f;
    }
}

// ---------------------------------------------------------------------------
// k_logits: dominant HBM-bound GEMV + exp + fused normalize.
// grid 512 (b = bx>>5, 32 blocks/batch), 128 thr (4 warps).
// Warp-private cp.async double-buffer pipelines, 16 rows/warp.
// Grid barrier, then each block normalizes its own 64 rows.
// ---------------------------------------------------------------------------
__global__ __launch_bounds__(128) void k_logits(const float* __restrict__ x,
                                                float* __restrict__ out) {
    __shared__ float buf[4][2][CC];
    __shared__ float vsm[CC];
    __shared__ float sp[128];
    const int b    = blockIdx.x >> 5;
    const int blk  = blockIdx.x & 31;
    const int tid  = threadIdx.x;
    const int warp = tid >> 5;
    const int lane = tid & 31;

    // stage v -> smem
    ((float4*)vsm)[tid]       = ((const float4*)(g_v + b * CC))[tid];
    ((float4*)vsm)[tid + 128] = ((const float4*)(g_v + b * CC))[tid + 128];

    const int row0 = blk * 64 + warp * 16;             // this warp's 16 rows
    const char* xw = (const char*)(x + ((size_t)b * NTOK + row0 + 1) * CC);
    const unsigned int sb =
        (unsigned int)__cvta_generic_to_shared(&buf[warp][0][0]);

    // prologue: rows 0 and 1
    #pragma unroll
    for (int k = 0; k < 8; k++)
        cpa16(sb + k * 512 + lane * 16, xw + k * 512 + lane * 16);
    CPA_COMMIT();
    #pragma unroll
    for (int k = 0; k < 8; k++)
        cpa16(sb + 4096 + k * 512 + lane * 16, xw + 4096 + k * 512 + lane * 16);
    CPA_COMMIT();

    __syncthreads();          // vsm ready
    float4 vr[8];
    #pragma unroll
    for (int i = 0; i < 8; i++) vr[i] = ((const float4*)vsm)[i * 32 + lane];

    float psum = 0.f;

    #pragma unroll
    for (int r = 0; r < 16; r++) {
        if (r == 15) { CPA_WAIT(0); } else { CPA_WAIT(1); }
        __syncwarp();

        const float4* bp = (const float4*)&buf[warp][r & 1][0];
        float4 a = make_float4(0.f, 0.f, 0.f, 0.f);
        #pragma unroll
        for (int i = 0; i < 8; i++) {
            const float4 xv = bp[i * 32 + lane];
            a.x = fmaf(xv.x, vr[i].x, a.x);
            a.y = fmaf(xv.y, vr[i].y, a.y);
            a.z = fmaf(xv.z, vr[i].z, a.z);
            a.w = fmaf(xv.w, vr[i].w, a.w);
        }
        float s = (a.x + a.y) + (a.z + a.w);
        #pragma unroll
        for (int o = 16; o; o >>= 1) s += __shfl_xor_sync(0xffffffffu, s, o);

        if (lane == 0) {
            const float e = __expf(s * 0.03125f);
            out[(b << 11) + row0 + r] = e;
            psum += e;
        }
        __syncwarp();         // readers done before overwrite

        if (r < 14) {
            const unsigned int dst = sb + (r & 1) * 4096;
            const char* src = xw + (size_t)(r + 2) * 4096;
            #pragma unroll
            for (int k = 0; k < 8; k++)
                cpa16(dst + k * 512 + lane * 16, src + k * 512 + lane * 16);
            CPA_COMMIT();
        }
    }

    if (lane == 0)
        g_psum[b * 128 + blk * 4 + warp] = psum;

    // ---------------- fused normalize ----------------
    gridbar(&g_barL, 512);

    sp[tid] = g_psum[b * 128 + tid];
    __syncthreads();
    #pragma unroll
    for (int o = 64; o; o >>= 1) {
        if (tid < o) sp[tid] += sp[tid + o];
        __syncthreads();
    }
    const float inv = 1.0f / sp[0];
    if (tid < 64)
        out[(b << 11) + blk * 64 + tid] *= inv;
}

// ---------------------------------------------------------------------------
extern "C" void kernel_launch(void* const* d_in, const int* in_sizes, int n_in,
                              void* d_out, int out_size) {
    const float* x = (const float*)d_in[0];
    const float* w = (const float*)d_in[1];
    if (n_in >= 2 && in_sizes[0] == CC * WS && in_sizes[1] == BB * NTOK * CC) {
        x = (const float*)d_in[1];
        w = (const float*)d_in[0];
    }
    float* out = (float*)d_out;

    k_prep  <<<128, 256>>>(x, w);
    k_logits<<<512, 128>>>(x, out);
}

// round 14
// speedup vs baseline: 1.2203x; 1.1568x over previous
#include <cuda_runtime.h>
#include <cstdint>

#define BB 16
#define NTOK 2049
#define NK 2048
#define CC 1024
#define WS 3072

__device__ float g_qcls[BB * CC];      // zero-init; atomic accum; re-zeroed by k_logits epilogue
__device__ float g_v[BB * CC];
__device__ float g_psum[BB * 512];     // exp partials: [b][bx*4+warp]
__device__ unsigned g_barP = 0;        // k_prep barrier counter (monotonic)
__device__ int g_cnt[BB] = {0};        // per-batch completion counters (reset by normalizer)

// ---------------------------------------------------------------------------
// helpers
// ---------------------------------------------------------------------------
__device__ __forceinline__ void cpa16(unsigned int smem_addr, const void* gptr) {
    asm volatile("cp.async.cg.shared.global [%0], [%1], 16;"
                 :: "r"(smem_addr), "l"(gptr));
}
#define CPA_COMMIT()  asm volatile("cp.async.commit_group;")
#define CPA_WAIT(N)   asm volatile("cp.async.wait_group %0;" :: "n"(N))

// Grid barrier via monotonic counter (replay-safe, all 256 blocks resident).
__device__ __forceinline__ void gridbar(unsigned* ctr, unsigned G) {
    __syncthreads();
    __threadfence();
    if (threadIdx.x == 0) {
        const unsigned my = atomicAdd(ctr, 1u) + 1u;
        const unsigned tgt = ((my - 1u) / G + 1u) * G;
        while (atomicAdd(ctr, 0u) < tgt) __nanosleep(64);
    }
    __syncthreads();
    __threadfence();
}

// ---------------------------------------------------------------------------
// k_prep: fused q_cls + v. grid 256, 256 thr (smem 34.8KB -> 6/SM, resident).
// Phase A: q_cls partials (W_q read once chip-wide), atomicAdd -> g_qcls.
// [grid barrier]
// Phase B: v[b,d] = W_k[d,:].q_cls[b,:]; block = (8 d, one bg of 8 batches).
// ---------------------------------------------------------------------------
__global__ __launch_bounds__(256) void k_prep(const float* __restrict__ x,
                                              const float* __restrict__ w) {
    __shared__ float pool[8704];
    const int t   = threadIdx.x;
    const int bid = blockIdx.x;
    const int wid = t >> 5, lane = t & 31;

    // ---------------- Phase A: q_cls partials ----------------
    {
        float* xs  = pool;                // [b][dd] 16x32
        float* red = pool + 512;          // [dg][b][c] 4x16x128
        const int d0 = (bid >> 3) * 32;
        const int c0 = (bid & 7) * 128;

        if (t < 128) {
            const int b = t >> 3, dd = (t & 7) * 4;
            *(float4*)&xs[b * 32 + dd] =
                *(const float4*)&x[(size_t)b * NTOK * CC + d0 + dd];
        }
        __syncthreads();

        const int dg = wid & 3, bg = wid >> 2;
        const int c = c0 + lane * 4;

        float4 a[8];
        #pragma unroll
        for (int j = 0; j < 8; j++) a[j] = make_float4(0.f, 0.f, 0.f, 0.f);

        const float* xb = &xs[bg * 8 * 32];
        #pragma unroll
        for (int i = 0; i < 8; i++) {
            const int dd = dg * 8 + i;
            const float4 w4 = *(const float4*)&w[(size_t)(d0 + dd) * WS + c];
            #pragma unroll
            for (int j = 0; j < 8; j++) {
                const float xv = xb[j * 32 + dd];
                a[j].x = fmaf(w4.x, xv, a[j].x);
                a[j].y = fmaf(w4.y, xv, a[j].y);
                a[j].z = fmaf(w4.z, xv, a[j].z);
                a[j].w = fmaf(w4.w, xv, a[j].w);
            }
        }
        #pragma unroll
        for (int j = 0; j < 8; j++)
            *(float4*)&red[dg * 2048 + (bg * 8 + j) * 128 + lane * 4] = a[j];
        __syncthreads();

        #pragma unroll
        for (int k = 0; k < 8; k++) {
            const int idx = t + 256 * k;             // b = idx>>7, c = idx&127
            const float s = (red[idx] + red[idx + 2048])
                          + (red[idx + 4096] + red[idx + 6144]);
            atomicAdd(&g_qcls[(idx >> 7) * CC + c0 + (idx & 127)], s);
        }
    }

    gridbar(&g_barP, 256);

    // ---------------- Phase B: v ----------------
    {
        float* qs = pool;                 // 8 batches x 1024 = 32KB
        const int bg = bid & 1;
        const int d  = (bid >> 1) * 8 + wid;

        #pragma unroll
        for (int i = 0; i < 8; i++)
            ((float4*)qs)[t + 256 * i] =
                ((const float4*)(g_qcls + bg * 8 * CC))[t + 256 * i];
        __syncthreads();

        const float* wr = w + (size_t)d * WS + CC;
        float acc[8];
        #pragma unroll
        for (int b = 0; b < 8; b++) acc[b] = 0.f;

        #pragma unroll
        for (int i = 0; i < 8; i++) {
            const int cc = i * 128 + lane * 4;
            const float4 w4 = *(const float4*)&wr[cc];
            #pragma unroll
            for (int b = 0; b < 8; b++) {
                const float4 q4 = *(const float4*)&qs[b * CC + cc];
                acc[b] = fmaf(w4.x, q4.x, acc[b]);
                acc[b] = fmaf(w4.y, q4.y, acc[b]);
                acc[b] = fmaf(w4.z, q4.z, acc[b]);
                acc[b] = fmaf(w4.w, q4.w, acc[b]);
            }
        }
        #pragma unroll
        for (int b = 0; b < 8; b++) {
            float a = acc[b];
            #pragma unroll
            for (int o = 16; o; o >>= 1) a += __shfl_xor_sync(0xffffffffu, a, o);
            if (lane == 0) g_v[(bg * 8 + b) * CC + d] = a;
        }
    }
}

// ---------------------------------------------------------------------------
// k_logits (dominant, HBM-bound): R11 shape — grid (128,16), 128 thr,
// block-wide 2-stage cp.async ring, 16 rows/block, warp computes 1 row/tile.
// Epilogue: last block per batch (atomic count, no barrier) reduces 512
// fixed-order psums, rescales its batch, zeroes g_qcls, resets counter.
// ---------------------------------------------------------------------------
__global__ __launch_bounds__(128) void k_logits(const float* __restrict__ x,
                                                float* __restrict__ out) {
    __shared__ float tiles[2 * 4096];
    __shared__ float vsm[CC];
    __shared__ float sp[128];
    __shared__ int lastflag;
    const int b    = blockIdx.y;
    const int bx   = blockIdx.x;
    const int tid  = threadIdx.x;
    const int warp = tid >> 5;
    const int lane = tid & 31;

    // stage v -> smem -> registers
    #pragma unroll
    for (int i = 0; i < 2; i++)
        ((float4*)vsm)[tid + 128 * i] = ((const float4*)(g_v + b * CC))[tid + 128 * i];

    const float* xbase = x + ((size_t)b * NTOK + bx * 16 + 1) * CC;
    const unsigned int sb = (unsigned int)__cvta_generic_to_shared(tiles);

    // prologue: tiles 0 and 1
    #pragma unroll
    for (int k = 0; k < 8; k++)
        cpa16(sb + (k * 512 + tid * 4) * 4, xbase + k * 512 + tid * 4);
    CPA_COMMIT();
    #pragma unroll
    for (int k = 0; k < 8; k++)
        cpa16(sb + (4096 + k * 512 + tid * 4) * 4, xbase + 4096 + k * 512 + tid * 4);
    CPA_COMMIT();

    __syncthreads();          // vsm ready
    float4 vr[8];
    #pragma unroll
    for (int i = 0; i < 8; i++) vr[i] = ((const float4*)vsm)[i * 32 + lane];

    float psum = 0.f;

    #pragma unroll
    for (int t = 0; t < 4; t++) {
        if (t == 3) { CPA_WAIT(0); } else { CPA_WAIT(1); }
        __syncthreads();

        const float* buf = tiles + (t & 1) * 4096 + warp * CC;
        float4 a = make_float4(0.f, 0.f, 0.f, 0.f);
        #pragma unroll
        for (int i = 0; i < 8; i++) {
            const float4 xv = ((const float4*)buf)[i * 32 + lane];
            a.x = fmaf(xv.x, vr[i].x, a.x);
            a.y = fmaf(xv.y, vr[i].y, a.y);
            a.z = fmaf(xv.z, vr[i].z, a.z);
            a.w = fmaf(xv.w, vr[i].w, a.w);
        }
        float s = (a.x + a.y) + (a.z + a.w);
        #pragma unroll
        for (int o = 16; o; o >>= 1) s += __shfl_xor_sync(0xffffffffu, s, o);

        if (lane == 0) {
            const float e = __expf(s * 0.03125f);
            out[(b << 11) + bx * 16 + t * 4 + warp] = e;
            psum += e;
        }

        if (t < 2) {
            __syncthreads();
            const int nt = t + 2;
            #pragma unroll
            for (int k = 0; k < 8; k++)
                cpa16(sb + ((nt & 1) * 4096 + k * 512 + tid * 4) * 4,
                      xbase + nt * 4096 + k * 512 + tid * 4);
            CPA_COMMIT();
        }
    }

    if (lane == 0)
        g_psum[b * 512 + bx * 4 + warp] = psum;

    // ---------------- last-block-per-batch normalize ----------------
    __threadfence();
    __syncthreads();
    if (tid == 0)
        lastflag = (atomicAdd(&g_cnt[b], 1) == 127);
    __syncthreads();

    if (lastflag) {
        const float* pp = g_psum + b * 512;
        float s = ((pp[tid] + pp[tid + 128]) + (pp[tid + 256] + pp[tid + 384]));
        sp[tid] = s;
        __syncthreads();
        #pragma unroll
        for (int o = 64; o; o >>= 1) {
            if (tid < o) sp[tid] += sp[tid + o];
            __syncthreads();
        }
        const float inv = 1.0f / sp[0];

        float4* ob = (float4*)(out + (b << 11));
        #pragma unroll
        for (int i = 0; i < 4; i++) {
            float4 v = ob[tid + 128 * i];
            v.x *= inv; v.y *= inv; v.z *= inv; v.w *= inv;
            ob[tid + 128 * i] = v;
        }

        // re-zero this batch's g_qcls slice for the next replay
        ((float4*)(g_qcls + b * CC))[tid]       = make_float4(0.f, 0.f, 0.f, 0.f);
        ((float4*)(g_qcls + b * CC))[tid + 128] = make_float4(0.f, 0.f, 0.f, 0.f);

        if (tid == 0) g_cnt[b] = 0;
    }
}

// ---------------------------------------------------------------------------
extern "C" void kernel_launch(void* const* d_in, const int* in_sizes, int n_in,
                              void* d_out, int out_size) {
    const float* x = (const float*)d_in[0];
    const float* w = (const float*)d_in[1];
    if (n_in >= 2 && in_sizes[0] == CC * WS && in_sizes[1] == BB * NTOK * CC) {
        x = (const float*)d_in[1];
        w = (const float*)d_in[0];
    }
    float* out = (float*)d_out;

    k_prep  <<<256, 256>>>(x, w);
    k_logits<<<dim3(128, 16), 128>>>(x, out);
}